// round 5
// baseline (speedup 1.0000x reference)
#include <cuda_runtime.h>

// Problem constants
#define B_   1024
#define I_   256
#define J_   256
#define K_   64

// Tiling
#define TB   128          // b per CTA
#define TJ   64           // j per CTA
#define ISPL 4            // i-splits (partial sums)
#define IPC  (I_ / ISPL)  // 64 i per CTA
#define NTHR 512
#define SROW 65           // smem row stride in floats (pad: 65 ≡ 1 mod 32)

// Scratch (static __device__ — no allocations allowed)
__device__ int4   g_prep[I_ * B_];                 // {w0,w1,off0(float idx),off1}  4 MB
__device__ float4 g_part4[ISPL * B_ * J_ / 4];     // i-split partial sums          4 MB

// ---------------------------------------------------------------------------
// Prep: per (i,b) compute searchsorted interval + lerp weights.
// Layout [i][b] so the main kernel's per-b fetch is a single uniform LDG.128.
// ---------------------------------------------------------------------------
__global__ void prep_kernel(const float* __restrict__ x, const float* __restrict__ Xg) {
    __shared__ float Xs[K_];
    int t = threadIdx.x;
    if (t < K_) Xs[t] = Xg[t];
    __syncthreads();

    int g = blockIdx.x * blockDim.x + t;      // g = i*B + b, exactly I_*B_ threads
    int i = g >> 10;                          // / B_
    int b = g & (B_ - 1);
    float xv = x[b * I_ + i];

    float X0 = Xs[0];
    float h  = (Xs[K_ - 1] - X0) / (float)(K_ - 1);
    int k = (int)floorf((xv - X0) / h);
    k = min(max(k, 0), K_ - 2);
    // exact fixup against the true grid (matches searchsorted side="right",
    // idx clipped to [1, K-1], k = idx-1)
    while (k > 0 && xv < Xs[k]) --k;
    while (k < K_ - 2 && xv >= Xs[k + 1]) ++k;

    float x0 = Xs[k], x1 = Xs[k + 1];
    float tt = (xv - x0) / (x1 - x0);         // may lie outside [0,1]: extrapolation
    int off0 = k * SROW;                      // float index of row k0 in smem tile
    g_prep[g] = make_int4(__float_as_int(1.0f - tt), __float_as_int(tt),
                          off0, off0 + SROW);
}

// ---------------------------------------------------------------------------
// Main: grid (ISPL, J_/TJ, B_/TB) = (4,4,8) = 128 CTAs, 512 threads.
// Per i: stage Y[i, j0:j0+64, :] (contiguous 16KB) transposed to Ys[k][jj],
// then each warp processes 8 b's with warp-uniform k0 -> conflict-free LDS.
// ---------------------------------------------------------------------------
__global__ void __launch_bounds__(NTHR, 1)
main_kernel(const float* __restrict__ Y) {
    __shared__ float Ys[2][K_ * SROW];        // double buffer: 2 * 16640 B

    const int it = blockIdx.x;                // i-split   0..3
    const int jt = blockIdx.y;                // j-tile    0..3
    const int bt = blockIdx.z;                // b-tile    0..7
    const int i0 = it * IPC;
    const int j0 = jt * TJ;
    const int b0 = bt * TB;

    const int tid  = threadIdx.x;
    const int w    = tid >> 5;
    const int lane = tid & 31;
    const int bw   = b0 + w * 8;              // warp's first b (8 b per warp)

    float2 acc[8];
    #pragma unroll
    for (int q = 0; q < 8; ++q) acc[q] = make_float2(0.f, 0.f);

    // stage tile for index i into buffer buf (transposed, stride SROW)
    auto load_tile = [&](int i, int buf) {
        const float4* src = (const float4*)(Y + (size_t)i * (J_ * K_) + (size_t)j0 * K_);
        #pragma unroll
        for (int r = 0; r < 2; ++r) {
            int t4 = tid + r * NTHR;          // 0..1023 float4s
            float4 v = src[t4];               // coalesced
            int f  = t4 << 2;                 // base float index in [0,4096)
            int jj = f >> 6;                  // source row (j within tile)
            int k  = f & 63;                  // source col (multiple of 4)
            float* dst = &Ys[buf][0];
            dst[(k + 0) * SROW + jj] = v.x;   // 2-way bank conflict (pad 65)
            dst[(k + 1) * SROW + jj] = v.y;
            dst[(k + 2) * SROW + jj] = v.z;
            dst[(k + 3) * SROW + jj] = v.w;
        }
    };

    load_tile(i0, 0);
    for (int ii = 0; ii < IPC; ++ii) {
        __syncthreads();
        if (ii + 1 < IPC) load_tile(i0 + ii + 1, (ii + 1) & 1);

        const int4*  pr   = g_prep + (size_t)(i0 + ii) * B_ + bw;
        const float* base = &Ys[ii & 1][0];
        #pragma unroll
        for (int bb = 0; bb < 8; ++bb) {
            int4 p = pr[bb];                  // warp-uniform LDG.128 (broadcast)
            float w0 = __int_as_float(p.x);
            float w1 = __int_as_float(p.y);
            const float* r0 = base + p.z;     // row k0
            const float* r1 = base + p.w;     // row k0+1
            // banks (k0 + lane) mod 32: conflict-free
            float y0a = r0[lane], y0b = r0[lane + 32];
            float y1a = r1[lane], y1b = r1[lane + 32];
            acc[bb].x = fmaf(w0, y0a, fmaf(w1, y1a, acc[bb].x));
            acc[bb].y = fmaf(w0, y0b, fmaf(w1, y1b, acc[bb].y));
        }
    }

    // write partials (deterministic; per-it slice, no atomics)
    float* part = (float*)g_part4 + (size_t)it * (B_ * J_);
    #pragma unroll
    for (int bb = 0; bb < 8; ++bb) {
        float* o = part + (size_t)(bw + bb) * J_ + j0;
        o[lane]      = acc[bb].x;             // j = j0 + lane
        o[lane + 32] = acc[bb].y;             // j = j0 + lane + 32
    }
}

// ---------------------------------------------------------------------------
// Reduce the ISPL partials into the output.
// ---------------------------------------------------------------------------
__global__ void reduce_kernel(float* __restrict__ out) {
    int g = blockIdx.x * blockDim.x + threadIdx.x;   // over B*J/4 float4s
    const int stride = B_ * J_ / 4;
    float4 a = g_part4[g];
    float4 b = g_part4[g + stride];
    float4 c = g_part4[g + 2 * stride];
    float4 d = g_part4[g + 3 * stride];
    float4 r;
    r.x = (a.x + b.x) + (c.x + d.x);
    r.y = (a.y + b.y) + (c.y + d.y);
    r.z = (a.z + b.z) + (c.z + d.z);
    r.w = (a.w + b.w) + (c.w + d.w);
    ((float4*)out)[g] = r;
}

// ---------------------------------------------------------------------------
extern "C" void kernel_launch(void* const* d_in, const int* in_sizes, int n_in,
                              void* d_out, int out_size) {
    const float* x  = (const float*)d_in[0];   // [B, I]
    const float* Xg = (const float*)d_in[1];   // [K]
    const float* Y  = (const float*)d_in[2];   // [I, J, K]
    float* out = (float*)d_out;                // [B, J]

    prep_kernel<<<(I_ * B_) / 256, 256>>>(x, Xg);
    main_kernel<<<dim3(ISPL, J_ / TJ, B_ / TB), NTHR>>>(Y);
    reduce_kernel<<<(B_ * J_ / 4) / 256, 256>>>(out);
}

// round 7
// speedup vs baseline: 1.2962x; 1.2962x over previous
#include <cuda_runtime.h>

// Problem constants
#define B_   1024
#define I_   256
#define J_   256
#define K_   64

// Tiling
#define TB   64            // b per CTA
#define TJ   64            // j per CTA
#define ISPL 4             // i-splits (partial sums)
#define IPC  (I_ / ISPL)   // 64 iterations per CTA
#define NTHR 256           // 8 warps, 8 b per warp
#define NBT  (B_ / TB)     // 16
#define NJT  (J_ / TJ)     // 4

// Static device scratch (no allocations allowed)
__device__ float        g_Yt[I_ * K_ * J_];             // Y transposed [i][k][j], 16.8 MB
__device__ int4         g_prep[I_ * B_];                // [i][b]: {w0,w1,off0B,off1B}
__device__ float4       g_part4[ISPL * B_ * J_ / 4];    // i-split partials
__device__ unsigned int g_cnt[NBT * NJT];               // last-block counters (self-resetting)

#define NT_BLOCKS (I_ * (J_ / 32) * (K_ / 32))          // 4096 transpose blocks
#define NP_BLOCKS ((B_ / 64) * (I_ / 64))               // 64 prep blocks

// ---------------------------------------------------------------------------
// pre_kernel: fused Y-transpose + interval/weight prep (disjoint block ranges
// run concurrently). Transpose: 32x32 fp32 tiles via smem, coalesced both
// sides, conflict-free smem (stride 33). Prep: smem-transposed x reads so both
// the x loads and the g_prep stores are coalesced.
// ---------------------------------------------------------------------------
__global__ void __launch_bounds__(256) pre_kernel(const float* __restrict__ x,
                                                  const float* __restrict__ Xg,
                                                  const float* __restrict__ Y) {
    const int bid = blockIdx.x;
    const int tid = threadIdx.x;

    if (bid < NT_BLOCKS) {
        // ---- transpose Y[i][j][k] -> Yt[i][k][j], one 32x32 tile ----
        __shared__ float s[32][33];
        const int i    = bid >> 4;
        const int rest = bid & 15;
        const int jb   = (rest >> 1) * 32;
        const int kb   = (rest & 1) * 32;
        const float* src = Y + (size_t)i * (J_ * K_);

        int jj = tid >> 3, kq = (tid & 7) << 2;
        float4 v = *(const float4*)(src + (size_t)(jb + jj) * K_ + kb + kq);
        s[jj][kq + 0] = v.x; s[jj][kq + 1] = v.y;
        s[jj][kq + 2] = v.z; s[jj][kq + 3] = v.w;
        __syncthreads();

        int k = tid >> 3, jq = (tid & 7) << 2;
        float4 o = make_float4(s[jq + 0][k], s[jq + 1][k], s[jq + 2][k], s[jq + 3][k]);
        *(float4*)(g_Yt + (size_t)i * (K_ * J_) + (size_t)(kb + k) * J_ + jb + jq) = o;
    } else {
        // ---- prep: 64 b x 64 i tile ----
        __shared__ float xs[64][65];
        __shared__ float Xs[K_];
        const int p  = bid - NT_BLOCKS;
        const int b0 = (p & 15) * 64;
        const int i0 = (p >> 4) * 64;
        if (tid < K_) Xs[tid] = Xg[tid];

        // Stage the FULL 64x64 x-tile: 4096 floats = 1024 float4s,
        // 256 threads x 4 float4s each. (Round-6 bug: only r=0 was loaded.)
        {
            int bb  = tid >> 2;                         // 0..63 (b row)
            int iq0 = (tid & 3) << 2;                   // 0,4,8,12
            #pragma unroll
            for (int r = 0; r < 4; ++r) {
                int iq = iq0 + r * 16;                  // covers 0..63
                float4 v = *(const float4*)(x + (size_t)(b0 + bb) * I_ + i0 + iq);
                xs[bb][iq + 0] = v.x; xs[bb][iq + 1] = v.y;
                xs[bb][iq + 2] = v.z; xs[bb][iq + 3] = v.w;
            }
        }
        __syncthreads();

        const int b  = tid & 63;
        const int ig = tid >> 6;
        const float X0   = Xs[0];
        const float hinv = (float)(K_ - 1) / (Xs[K_ - 1] - X0);
        #pragma unroll 4
        for (int q = 0; q < 16; ++q) {
            int   i  = ig * 16 + q;
            float xv = xs[b][i];                        // conflict-free (stride 65)
            int k = (int)floorf((xv - X0) * hinv);
            k = min(max(k, 0), K_ - 2);
            // exact fixup vs true grid (matches searchsorted side="right",
            // idx clipped to [1,K-1])
            while (k > 0 && xv < Xs[k]) --k;
            while (k < K_ - 2 && xv >= Xs[k + 1]) ++k;
            float x0 = Xs[k], x1 = Xs[k + 1];
            float tt = (xv - x0) / (x1 - x0);           // extrapolates at edges
            int off0 = k * (J_ * 4);                    // byte offset of row k in Yt i-block
            g_prep[(size_t)(i0 + i) * B_ + b0 + b] =
                make_int4(__float_as_int(1.0f - tt), __float_as_int(tt),
                          off0, off0 + J_ * 4);
        }
    }
}

// ---------------------------------------------------------------------------
// main_kernel: no smem staging, no __syncthreads in the mainloop.
// Grid (16,4,4) = 256 CTAs, 256 threads, occupancy 2.
// Per warp: 8 b, each b needs 2 contiguous 256B rows of Yt -> LDG.64 per
// thread (j = 2*lane, 2*lane+1), L1-resident tile reuse across 64 b's.
// Packed f32x2 FMA. Last CTA per (bt,jt) reduces the ISPL partials.
// ---------------------------------------------------------------------------
__global__ void __launch_bounds__(NTHR, 2)
main_kernel(float* __restrict__ outp) {
    const int bt = blockIdx.x;                 // 0..15
    const int jt = blockIdx.y;                 // 0..3
    const int it = blockIdx.z;                 // 0..3
    const int i0 = it * IPC;
    const int j0 = jt * TJ;
    const int b0 = bt * TB;

    const int w    = threadIdx.x >> 5;
    const int lane = threadIdx.x & 31;
    const int bw   = b0 + w * 8;               // warp's 8 b's

    unsigned long long acc[8];
    #pragma unroll
    for (int q = 0; q < 8; ++q) acc[q] = 0ULL;  // {0.f, 0.f}

    const char* ybase = (const char*)g_Yt
                      + ((size_t)i0 * (K_ * J_) + j0 + 2 * lane) * 4;
    const int4* pp = g_prep + (size_t)i0 * B_ + bw;

    for (int ii = 0; ii < IPC; ++ii) {
        #pragma unroll
        for (int bb = 0; bb < 8; ++bb) {
            int4 p = pp[bb];                   // warp-uniform LDG.128
            unsigned long long y0 = *(const unsigned long long*)(ybase + p.z);
            unsigned long long y1 = *(const unsigned long long*)(ybase + p.w);
            unsigned long long W0, W1;
            asm("mov.b64 %0, {%1, %1};" : "=l"(W0) : "r"(p.x));
            asm("mov.b64 %0, {%1, %1};" : "=l"(W1) : "r"(p.y));
            asm("fma.rn.f32x2 %0, %1, %2, %0;" : "+l"(acc[bb]) : "l"(W0), "l"(y0));
            asm("fma.rn.f32x2 %0, %1, %2, %0;" : "+l"(acc[bb]) : "l"(W1), "l"(y1));
        }
        ybase += K_ * J_ * 4;
        pp    += B_;
    }

    // write partial sums (deterministic, per-it slice)
    float* part = (float*)g_part4 + (size_t)it * (B_ * J_);
    #pragma unroll
    for (int bb = 0; bb < 8; ++bb) {
        *(unsigned long long*)(part + (size_t)(bw + bb) * J_ + j0 + 2 * lane) = acc[bb];
    }

    // ---- fused last-block reduction over the ISPL partials ----
    __shared__ unsigned int s_last;
    __threadfence();                           // publish partials (release)
    if (threadIdx.x == 0) {
        unsigned int old = atomicAdd(&g_cnt[bt * NJT + jt], 1u);
        s_last = (old == ISPL - 1) ? 1u : 0u;
    }
    __syncthreads();
    if (s_last) {
        __threadfence();                       // acquire other CTAs' partials
        if (threadIdx.x == 0) g_cnt[bt * NJT + jt] = 0;   // self-reset for replay
        const int stride = B_ * J_ / 4;
        for (int t = threadIdx.x; t < TB * TJ / 4; t += NTHR) {
            int row = t >> 4;                  // 0..63   (TJ/4 = 16)
            int c4  = t & 15;
            size_t idx = (((size_t)(b0 + row) * J_ + j0) >> 2) + c4;
            float4 a = g_part4[idx];
            float4 b = g_part4[idx + stride];
            float4 c = g_part4[idx + 2 * stride];
            float4 d = g_part4[idx + 3 * stride];
            float4 r;
            r.x = (a.x + b.x) + (c.x + d.x);
            r.y = (a.y + b.y) + (c.y + d.y);
            r.z = (a.z + b.z) + (c.z + d.z);
            r.w = (a.w + b.w) + (c.w + d.w);
            ((float4*)outp)[idx] = r;
        }
    }
}

// ---------------------------------------------------------------------------
extern "C" void kernel_launch(void* const* d_in, const int* in_sizes, int n_in,
                              void* d_out, int out_size) {
    const float* x  = (const float*)d_in[0];   // [B, I]
    const float* Xg = (const float*)d_in[1];   // [K]
    const float* Y  = (const float*)d_in[2];   // [I, J, K]
    float* out = (float*)d_out;                // [B, J]

    pre_kernel<<<NT_BLOCKS + NP_BLOCKS, 256>>>(x, Xg, Y);
    main_kernel<<<dim3(NBT, NJT, ISPL), NTHR>>>(out);
}

// round 8
// speedup vs baseline: 1.3635x; 1.0519x over previous
#include <cuda_runtime.h>

// Problem constants
#define B_   1024
#define I_   256
#define J_   256
#define K_   64

// Tiling
#define TB   64            // b per CTA
#define TJ   64            // j per CTA
#define ISPL 4             // i-splits (partial sums)
#define IPC  (I_ / ISPL)   // 64 iterations per CTA
#define NTHR 512           // 16 warps, 4 b per warp
#define BPW  4             // b's per warp
#define NBT  (B_ / TB)     // 16
#define NJT  (J_ / TJ)     // 4

// Static device scratch (no allocations allowed)
__device__ float        g_Yt[I_ * K_ * J_];             // Y transposed [i][k][j], 16.8 MB
__device__ int4         g_prep[I_ * B_];                // [i][b]: {w0,w1,off0B,off1B}
__device__ float4       g_part4[ISPL * B_ * J_ / 4];    // i-split partials
__device__ unsigned int g_cnt[NBT * NJT];               // last-block counters (self-resetting)

#define NT_BLOCKS (I_ * (J_ / 32) * (K_ / 32))          // 4096 transpose blocks
#define NP_BLOCKS ((B_ / 64) * (I_ / 64))               // 64 prep blocks

// ---------------------------------------------------------------------------
// pre_kernel: fused Y-transpose + interval/weight prep (disjoint block ranges
// run concurrently). Transpose: 32x32 fp32 tiles via smem, coalesced both
// sides, conflict-free smem (stride 33). Prep: smem-transposed x reads so both
// the x loads and the g_prep stores are coalesced.
// ---------------------------------------------------------------------------
__global__ void __launch_bounds__(256) pre_kernel(const float* __restrict__ x,
                                                  const float* __restrict__ Xg,
                                                  const float* __restrict__ Y) {
    const int bid = blockIdx.x;
    const int tid = threadIdx.x;

    if (bid < NT_BLOCKS) {
        // ---- transpose Y[i][j][k] -> Yt[i][k][j], one 32x32 tile ----
        __shared__ float s[32][33];
        const int i    = bid >> 4;
        const int rest = bid & 15;
        const int jb   = (rest >> 1) * 32;
        const int kb   = (rest & 1) * 32;
        const float* src = Y + (size_t)i * (J_ * K_);

        int jj = tid >> 3, kq = (tid & 7) << 2;
        float4 v = *(const float4*)(src + (size_t)(jb + jj) * K_ + kb + kq);
        s[jj][kq + 0] = v.x; s[jj][kq + 1] = v.y;
        s[jj][kq + 2] = v.z; s[jj][kq + 3] = v.w;
        __syncthreads();

        int k = tid >> 3, jq = (tid & 7) << 2;
        float4 o = make_float4(s[jq + 0][k], s[jq + 1][k], s[jq + 2][k], s[jq + 3][k]);
        *(float4*)(g_Yt + (size_t)i * (K_ * J_) + (size_t)(kb + k) * J_ + jb + jq) = o;
    } else {
        // ---- prep: 64 b x 64 i tile ----
        __shared__ float xs[64][65];
        __shared__ float Xs[K_];
        const int p  = bid - NT_BLOCKS;
        const int b0 = (p & 15) * 64;
        const int i0 = (p >> 4) * 64;
        if (tid < K_) Xs[tid] = Xg[tid];

        // Stage the FULL 64x64 x-tile: 1024 float4s, 256 threads x 4.
        {
            int bb  = tid >> 2;                         // 0..63 (b row)
            int iq0 = (tid & 3) << 2;                   // 0,4,8,12
            #pragma unroll
            for (int r = 0; r < 4; ++r) {
                int iq = iq0 + r * 16;                  // covers 0..63
                float4 v = *(const float4*)(x + (size_t)(b0 + bb) * I_ + i0 + iq);
                xs[bb][iq + 0] = v.x; xs[bb][iq + 1] = v.y;
                xs[bb][iq + 2] = v.z; xs[bb][iq + 3] = v.w;
            }
        }
        __syncthreads();

        const int b  = tid & 63;
        const int ig = tid >> 6;
        const float X0   = Xs[0];
        const float hinv = (float)(K_ - 1) / (Xs[K_ - 1] - X0);
        #pragma unroll 4
        for (int q = 0; q < 16; ++q) {
            int   i  = ig * 16 + q;
            float xv = xs[b][i];                        // conflict-free (stride 65)
            int k = (int)floorf((xv - X0) * hinv);
            k = min(max(k, 0), K_ - 2);
            // exact fixup vs true grid (matches searchsorted side="right",
            // idx clipped to [1,K-1])
            while (k > 0 && xv < Xs[k]) --k;
            while (k < K_ - 2 && xv >= Xs[k + 1]) ++k;
            float x0 = Xs[k], x1 = Xs[k + 1];
            float tt = (xv - x0) / (x1 - x0);           // extrapolates at edges
            int off0 = k * (J_ * 4);                    // byte offset of row k in Yt i-block
            g_prep[(size_t)(i0 + i) * B_ + b0 + b] =
                make_int4(__float_as_int(1.0f - tt), __float_as_int(tt),
                          off0, off0 + J_ * 4);
        }
    }
}

// ---------------------------------------------------------------------------
// main_kernel: no smem staging, no __syncthreads in the mainloop.
// Grid (16,4,4) = 256 CTAs, 512 threads, 16 warps x 4 b per warp.
// __launch_bounds__(512,2) -> <=64 regs -> 1024 thr/SM (8 warps/SMSP),
// doubling the latency-hiding pool vs round 7 (occ was the bottleneck:
// 20.8% occ / 18.7% issue / 55% l1tex).
// Packed f32x2 FMA. Last CTA per (bt,jt) reduces the ISPL partials.
// ---------------------------------------------------------------------------
__global__ void __launch_bounds__(NTHR, 2)
main_kernel(float* __restrict__ outp) {
    const int bt = blockIdx.x;                 // 0..15
    const int jt = blockIdx.y;                 // 0..3
    const int it = blockIdx.z;                 // 0..3
    const int i0 = it * IPC;
    const int j0 = jt * TJ;
    const int b0 = bt * TB;

    const int w    = threadIdx.x >> 5;         // 0..15
    const int lane = threadIdx.x & 31;
    const int bw   = b0 + w * BPW;             // warp's 4 b's

    unsigned long long acc[BPW];
    #pragma unroll
    for (int q = 0; q < BPW; ++q) acc[q] = 0ULL;   // {0.f, 0.f}

    const char* ybase = (const char*)g_Yt
                      + ((size_t)i0 * (K_ * J_) + j0 + 2 * lane) * 4;
    const int4* pp = g_prep + (size_t)i0 * B_ + bw;

    for (int ii = 0; ii < IPC; ++ii) {
        // fetch all preps first (independent, broadcast LDG.128)
        int4 p[BPW];
        #pragma unroll
        for (int bb = 0; bb < BPW; ++bb) p[bb] = pp[bb];
        #pragma unroll
        for (int bb = 0; bb < BPW; ++bb) {
            unsigned long long y0 = *(const unsigned long long*)(ybase + p[bb].z);
            unsigned long long y1 = *(const unsigned long long*)(ybase + p[bb].w);
            unsigned long long W0, W1;
            asm("mov.b64 %0, {%1, %1};" : "=l"(W0) : "r"(p[bb].x));
            asm("mov.b64 %0, {%1, %1};" : "=l"(W1) : "r"(p[bb].y));
            asm("fma.rn.f32x2 %0, %1, %2, %0;" : "+l"(acc[bb]) : "l"(W0), "l"(y0));
            asm("fma.rn.f32x2 %0, %1, %2, %0;" : "+l"(acc[bb]) : "l"(W1), "l"(y1));
        }
        ybase += K_ * J_ * 4;
        pp    += B_;
    }

    // write partial sums (deterministic, per-it slice)
    float* part = (float*)g_part4 + (size_t)it * (B_ * J_);
    #pragma unroll
    for (int bb = 0; bb < BPW; ++bb) {
        *(unsigned long long*)(part + (size_t)(bw + bb) * J_ + j0 + 2 * lane) = acc[bb];
    }

    // ---- fused last-block reduction over the ISPL partials ----
    __shared__ unsigned int s_last;
    __threadfence();                           // publish partials (release)
    if (threadIdx.x == 0) {
        unsigned int old = atomicAdd(&g_cnt[bt * NJT + jt], 1u);
        s_last = (old == ISPL - 1) ? 1u : 0u;
    }
    __syncthreads();
    if (s_last) {
        __threadfence();                       // acquire other CTAs' partials
        if (threadIdx.x == 0) g_cnt[bt * NJT + jt] = 0;   // self-reset for replay
        const int stride = B_ * J_ / 4;
        for (int t = threadIdx.x; t < TB * TJ / 4; t += NTHR) {
            int row = t >> 4;                  // 0..63   (TJ/4 = 16)
            int c4  = t & 15;
            size_t idx = (((size_t)(b0 + row) * J_ + j0) >> 2) + c4;
            float4 a = g_part4[idx];
            float4 b = g_part4[idx + stride];
            float4 c = g_part4[idx + 2 * stride];
            float4 d = g_part4[idx + 3 * stride];
            float4 r;
            r.x = (a.x + b.x) + (c.x + d.x);
            r.y = (a.y + b.y) + (c.y + d.y);
            r.z = (a.z + b.z) + (c.z + d.z);
            r.w = (a.w + b.w) + (c.w + d.w);
            ((float4*)outp)[idx] = r;
        }
    }
}

// ---------------------------------------------------------------------------
extern "C" void kernel_launch(void* const* d_in, const int* in_sizes, int n_in,
                              void* d_out, int out_size) {
    const float* x  = (const float*)d_in[0];   // [B, I]
    const float* Xg = (const float*)d_in[1];   // [K]
    const float* Y  = (const float*)d_in[2];   // [I, J, K]
    float* out = (float*)d_out;                // [B, J]

    pre_kernel<<<NT_BLOCKS + NP_BLOCKS, 256>>>(x, Xg, Y);
    main_kernel<<<dim3(NBT, NJT, ISPL), NTHR>>>(out);
}

// round 9
// speedup vs baseline: 1.6399x; 1.2028x over previous
#include <cuda_runtime.h>

// Problem constants
#define B_   1024
#define I_   256
#define J_   256
#define K_   64

// Tiling
#define TB   64            // b per CTA
#define TJ   64            // j per CTA
#define ISPL 4             // i-splits (partial sums)
#define IPC  (I_ / ISPL)   // 64 iterations per CTA
#define NTHR 512           // 16 warps, 4 b per warp
#define BPW  4             // b's per warp
#define NBT  (B_ / TB)     // 16
#define NJT  (J_ / TJ)     // 4

// Static device scratch (no allocations allowed)
__device__ float        g_Yt[I_ * K_ * J_];             // Y transposed [i][k][j], 16.8 MB
__device__ int4         g_prep[I_ * B_];                // [i][b]: {w0,w1,off0B,off1B}
__device__ float4       g_part4[ISPL * B_ * J_ / 4];    // i-split partials
__device__ unsigned int g_cnt[NBT * NJT];               // last-block counters (self-resetting)

#define NT_BLOCKS (I_ * (J_ / 32) * (K_ / 32))          // 4096 transpose blocks
#define NP_BLOCKS ((B_ / 64) * (I_ / 64))               // 64 prep blocks

// ---------------------------------------------------------------------------
// pre_kernel: fused Y-transpose + interval/weight prep (disjoint block ranges
// run concurrently). Transpose: 32x32 fp32 tiles via smem, coalesced both
// sides, conflict-free smem (stride 33). Prep: smem-transposed x reads so both
// the x loads and the g_prep stores are coalesced.
// ---------------------------------------------------------------------------
__global__ void __launch_bounds__(256) pre_kernel(const float* __restrict__ x,
                                                  const float* __restrict__ Xg,
                                                  const float* __restrict__ Y) {
    const int bid = blockIdx.x;
    const int tid = threadIdx.x;

    if (bid < NT_BLOCKS) {
        // ---- transpose Y[i][j][k] -> Yt[i][k][j], one 32x32 tile ----
        __shared__ float s[32][33];
        const int i    = bid >> 4;
        const int rest = bid & 15;
        const int jb   = (rest >> 1) * 32;
        const int kb   = (rest & 1) * 32;
        const float* src = Y + (size_t)i * (J_ * K_);

        int jj = tid >> 3, kq = (tid & 7) << 2;
        float4 v = *(const float4*)(src + (size_t)(jb + jj) * K_ + kb + kq);
        s[jj][kq + 0] = v.x; s[jj][kq + 1] = v.y;
        s[jj][kq + 2] = v.z; s[jj][kq + 3] = v.w;
        __syncthreads();

        int k = tid >> 3, jq = (tid & 7) << 2;
        float4 o = make_float4(s[jq + 0][k], s[jq + 1][k], s[jq + 2][k], s[jq + 3][k]);
        *(float4*)(g_Yt + (size_t)i * (K_ * J_) + (size_t)(kb + k) * J_ + jb + jq) = o;
    } else {
        // ---- prep: 64 b x 64 i tile ----
        __shared__ float xs[64][65];
        __shared__ float Xs[K_];
        const int p  = bid - NT_BLOCKS;
        const int b0 = (p & 15) * 64;
        const int i0 = (p >> 4) * 64;
        if (tid < K_) Xs[tid] = Xg[tid];

        // Stage the FULL 64x64 x-tile: 1024 float4s, 256 threads x 4.
        {
            int bb  = tid >> 2;                         // 0..63 (b row)
            int iq0 = (tid & 3) << 2;                   // 0,4,8,12
            #pragma unroll
            for (int r = 0; r < 4; ++r) {
                int iq = iq0 + r * 16;                  // covers 0..63
                float4 v = *(const float4*)(x + (size_t)(b0 + bb) * I_ + i0 + iq);
                xs[bb][iq + 0] = v.x; xs[bb][iq + 1] = v.y;
                xs[bb][iq + 2] = v.z; xs[bb][iq + 3] = v.w;
            }
        }
        __syncthreads();

        const int b  = tid & 63;
        const int ig = tid >> 6;
        const float X0   = Xs[0];
        const float hinv = (float)(K_ - 1) / (Xs[K_ - 1] - X0);
        #pragma unroll 4
        for (int q = 0; q < 16; ++q) {
            int   i  = ig * 16 + q;
            float xv = xs[b][i];                        // conflict-free (stride 65)
            int k = (int)floorf((xv - X0) * hinv);
            k = min(max(k, 0), K_ - 2);
            // exact fixup vs true grid (matches searchsorted side="right",
            // idx clipped to [1,K-1])
            while (k > 0 && xv < Xs[k]) --k;
            while (k < K_ - 2 && xv >= Xs[k + 1]) ++k;
            float x0 = Xs[k], x1 = Xs[k + 1];
            float tt = (xv - x0) / (x1 - x0);           // extrapolates at edges
            int off0 = k * (J_ * 4);                    // byte offset of row k in Yt i-block
            g_prep[(size_t)(i0 + i) * B_ + b0 + b] =
                make_int4(__float_as_int(1.0f - tt), __float_as_int(tt),
                          off0, off0 + J_ * 4);
        }
    }
}

// ---------------------------------------------------------------------------
// main_kernel: grid (16,4,4) = 256 CTAs, 512 threads, 16 warps x 4 b.
// Round-9 change: the whole per-CTA prep slab (IPC x TB int4 = 64KB) is
// staged into smem ONCE up front. The mainloop then has no prep LDGs and no
// prep->y dependency chain: per iteration it's 4 broadcast LDS.128 (29cyc,
// short scoreboard) + 8 independent y LDG.64s (MLP 8) + 8 FFMA2.
// Last CTA per (bt,jt) reduces the ISPL partials (deterministic order).
// ---------------------------------------------------------------------------
__global__ void __launch_bounds__(NTHR, 2)
main_kernel(float* __restrict__ outp) {
    __shared__ int4 s_prep[IPC][TB];           // 64 KB: fits at occupancy 2
    __shared__ unsigned int s_last;

    const int bt = blockIdx.x;                 // 0..15
    const int jt = blockIdx.y;                 // 0..3
    const int it = blockIdx.z;                 // 0..3
    const int i0 = it * IPC;
    const int j0 = jt * TJ;
    const int b0 = bt * TB;

    const int w    = threadIdx.x >> 5;         // 0..15
    const int lane = threadIdx.x & 31;

    // ---- stage prep slab: 4096 int4s, 512 threads x 8 coalesced rounds ----
    {
        const int4* gp = g_prep + (size_t)i0 * B_ + b0;
        #pragma unroll
        for (int r = 0; r < (IPC * TB) / NTHR; ++r) {
            int flat = threadIdx.x + r * NTHR;
            int ii = flat >> 6;                // / TB
            int b  = flat & (TB - 1);
            s_prep[ii][b] = gp[(size_t)ii * B_ + b];
        }
    }
    __syncthreads();

    unsigned long long acc[BPW];
    #pragma unroll
    for (int q = 0; q < BPW; ++q) acc[q] = 0ULL;   // {0.f, 0.f}

    const char* ybase = (const char*)g_Yt
                      + ((size_t)i0 * (K_ * J_) + j0 + 2 * lane) * 4;
    const int wb = w * BPW;                    // warp's first local b

    for (int ii = 0; ii < IPC; ++ii) {
        int4 p[BPW];
        #pragma unroll
        for (int bb = 0; bb < BPW; ++bb) p[bb] = s_prep[ii][wb + bb];   // LDS broadcast
        #pragma unroll
        for (int bb = 0; bb < BPW; ++bb) {
            unsigned long long y0 = *(const unsigned long long*)(ybase + p[bb].z);
            unsigned long long y1 = *(const unsigned long long*)(ybase + p[bb].w);
            unsigned long long W0, W1;
            asm("mov.b64 %0, {%1, %1};" : "=l"(W0) : "r"(p[bb].x));
            asm("mov.b64 %0, {%1, %1};" : "=l"(W1) : "r"(p[bb].y));
            asm("fma.rn.f32x2 %0, %1, %2, %0;" : "+l"(acc[bb]) : "l"(W0), "l"(y0));
            asm("fma.rn.f32x2 %0, %1, %2, %0;" : "+l"(acc[bb]) : "l"(W1), "l"(y1));
        }
        ybase += K_ * J_ * 4;
    }

    // write partial sums (deterministic, per-it slice)
    float* part = (float*)g_part4 + (size_t)it * (B_ * J_);
    const int bw = b0 + wb;
    #pragma unroll
    for (int bb = 0; bb < BPW; ++bb) {
        *(unsigned long long*)(part + (size_t)(bw + bb) * J_ + j0 + 2 * lane) = acc[bb];
    }

    // ---- fused last-block reduction over the ISPL partials ----
    __threadfence();                           // publish partials (release)
    if (threadIdx.x == 0) {
        unsigned int old = atomicAdd(&g_cnt[bt * NJT + jt], 1u);
        s_last = (old == ISPL - 1) ? 1u : 0u;
    }
    __syncthreads();
    if (s_last) {
        __threadfence();                       // acquire other CTAs' partials
        if (threadIdx.x == 0) g_cnt[bt * NJT + jt] = 0;   // self-reset for replay
        const int stride = B_ * J_ / 4;
        for (int t = threadIdx.x; t < TB * TJ / 4; t += NTHR) {
            int row = t >> 4;                  // 0..63   (TJ/4 = 16)
            int c4  = t & 15;
            size_t idx = (((size_t)(b0 + row) * J_ + j0) >> 2) + c4;
            float4 a = g_part4[idx];
            float4 b = g_part4[idx + stride];
            float4 c = g_part4[idx + 2 * stride];
            float4 d = g_part4[idx + 3 * stride];
            float4 r;
            r.x = (a.x + b.x) + (c.x + d.x);
            r.y = (a.y + b.y) + (c.y + d.y);
            r.z = (a.z + b.z) + (c.z + d.z);
            r.w = (a.w + b.w) + (c.w + d.w);
            ((float4*)outp)[idx] = r;
        }
    }
}

// ---------------------------------------------------------------------------
extern "C" void kernel_launch(void* const* d_in, const int* in_sizes, int n_in,
                              void* d_out, int out_size) {
    const float* x  = (const float*)d_in[0];   // [B, I]
    const float* Xg = (const float*)d_in[1];   // [K]
    const float* Y  = (const float*)d_in[2];   // [I, J, K]
    float* out = (float*)d_out;                // [B, J]

    pre_kernel<<<NT_BLOCKS + NP_BLOCKS, 256>>>(x, Xg, Y);
    main_kernel<<<dim3(NBT, NJT, ISPL), NTHR>>>(out);
}